// round 4
// baseline (speedup 1.0000x reference)
#include <cuda_runtime.h>
#include <cuda_bf16.h>

// Inputs (metadata order):
//   d_in[0]: pre     float32  [N, 3]   (log-softmax)
//   d_in[1]: y_true  int32    [N]
//   d_in[2]: weight  float32  scalar
// Output: float32 scalar = -sum(w_i * pre[i, y_i]) / N,
//   w_i = weight if |argmax(pre_i) - y_i| == 2 else 1.

#define NBLOCKS 2048
#define NTHREADS 256

__device__ float g_partials[NBLOCKS];
__device__ unsigned int g_done_count;   // static zero-init; reset by last block

__device__ __forceinline__ float row_term(float a, float b, float c, int yt, float w) {
    // argmax with first-occurrence tie-breaking (strict >)
    int pred = 0;
    float best = a;
    if (b > best) { best = b; pred = 1; }
    if (c > best) { pred = 2; }
    float picked = (yt == 0) ? a : ((yt == 1) ? b : c);
    int d = pred - yt;
    bool penal = (d == 2) || (d == -2);
    return penal ? (w * picked) : picked;
}

__device__ __forceinline__ float quad_term(float4 f0, float4 f1, float4 f2,
                                           int4 yv, float w) {
    float t = 0.0f;
    t += row_term(f0.x, f0.y, f0.z, yv.x, w);
    t += row_term(f0.w, f1.x, f1.y, yv.y, w);
    t += row_term(f1.z, f1.w, f2.x, yv.z, w);
    t += row_term(f2.y, f2.z, f2.w, yv.w, w);
    return t;
}

__global__ void __launch_bounds__(NTHREADS)
nll_fused_kernel(const float* __restrict__ pre,
                 const int* __restrict__ y,
                 const float* __restrict__ wp,
                 float* __restrict__ out,
                 int n, float inv_n_neg) {
    const float4* p4 = reinterpret_cast<const float4*>(pre);
    const int4*   y4 = reinterpret_cast<const int4*>(y);
    const float w = *wp;

    const int nquad  = n >> 2;
    const int tid    = blockIdx.x * blockDim.x + threadIdx.x;
    const int stride = gridDim.x * blockDim.x;

    float acc = 0.0f;

    if (nquad == 4 * stride && (n & 3) == 0) {
        // Exact-fit fast path: each thread owns quads tid + u*stride, u=0..3.
        // Front-batch all 16 independent LDG.128 to maximize MLP.
        float4 f[12];
        int4   yv[4];
        #pragma unroll
        for (int u = 0; u < 4; u++) {
            int q = tid + u * stride;
            f[3 * u + 0] = p4[3 * q + 0];
            f[3 * u + 1] = p4[3 * q + 1];
            f[3 * u + 2] = p4[3 * q + 2];
            yv[u]        = y4[q];
        }
        #pragma unroll
        for (int u = 0; u < 4; u++)
            acc += quad_term(f[3 * u], f[3 * u + 1], f[3 * u + 2], yv[u], w);
    } else {
        // generic fallback
        for (int q = tid; q < nquad; q += stride) {
            float4 f0 = p4[3 * q + 0];
            float4 f1 = p4[3 * q + 1];
            float4 f2 = p4[3 * q + 2];
            acc += quad_term(f0, f1, f2, y4[q], w);
        }
        for (int i = (nquad << 2) + tid; i < n; i += stride)
            acc += row_term(pre[3 * i + 0], pre[3 * i + 1], pre[3 * i + 2], y[i], w);
    }

    // intra-block reduction
    #pragma unroll
    for (int off = 16; off > 0; off >>= 1)
        acc += __shfl_down_sync(0xFFFFFFFFu, acc, off);

    __shared__ float s[NTHREADS / 32];
    __shared__ bool s_last;
    int lane = threadIdx.x & 31;
    int wid  = threadIdx.x >> 5;
    if (lane == 0) s[wid] = acc;
    __syncthreads();

    if (wid == 0) {
        float v = (lane < NTHREADS / 32) ? s[lane] : 0.0f;
        #pragma unroll
        for (int off = 16; off > 0; off >>= 1)
            v += __shfl_down_sync(0xFFFFFFFFu, v, off);
        if (lane == 0) {
            g_partials[blockIdx.x] = v;
            __threadfence();
            unsigned int prev = atomicAdd(&g_done_count, 1u);
            s_last = (prev == (unsigned int)(gridDim.x - 1));
        }
    }
    __syncthreads();

    // last block folds all partials (deterministic fixed order)
    if (s_last) {
        float v = 0.0f;
        #pragma unroll
        for (int k = threadIdx.x; k < NBLOCKS; k += NTHREADS)
            v += g_partials[k];

        #pragma unroll
        for (int off = 16; off > 0; off >>= 1)
            v += __shfl_down_sync(0xFFFFFFFFu, v, off);

        if (lane == 0) s[wid] = v;
        __syncthreads();
        if (wid == 0) {
            float t = (lane < NTHREADS / 32) ? s[lane] : 0.0f;
            #pragma unroll
            for (int off = 16; off > 0; off >>= 1)
                t += __shfl_down_sync(0xFFFFFFFFu, t, off);
            if (lane == 0) {
                out[0] = t * inv_n_neg;      // = -sum / N
                g_done_count = 0u;           // reset for next graph replay
            }
        }
    }
}

extern "C" void kernel_launch(void* const* d_in, const int* in_sizes, int n_in,
                              void* d_out, int out_size) {
    const float* pre = (const float*)d_in[0];
    const int*   y   = (const int*)d_in[1];
    const float* wp  = (const float*)d_in[2];
    float* out = (float*)d_out;

    const int n = in_sizes[1];   // y_true element count = number of rows

    nll_fused_kernel<<<NBLOCKS, NTHREADS>>>(pre, y, wp, out, n, -1.0f / (float)n);
}

// round 5
// speedup vs baseline: 1.0055x; 1.0055x over previous
#include <cuda_runtime.h>
#include <cuda_bf16.h>
#include <cstdint>

// Inputs (metadata order):
//   d_in[0]: pre     float32  [N, 3]   (log-softmax)
//   d_in[1]: y_true  int32    [N]
//   d_in[2]: weight  float32  scalar
// Output: float32 scalar = -sum(w_i * pre[i, y_i]) / N,
//   w_i = weight if |argmax(pre_i) - y_i| == 2 else 1.

#define NBLOCKS 2048
#define NTHREADS 256
#define ROWS_PER_TILE 1024
#define TILES_PER_BLOCK 4
#define PRE_TILE_BYTES (ROWS_PER_TILE * 12)
#define Y_TILE_BYTES   (ROWS_PER_TILE * 4)
#define STAGE_TX_BYTES (PRE_TILE_BYTES + Y_TILE_BYTES)

__device__ float g_partials[NBLOCKS];
__device__ unsigned int g_done_count;   // static zero-init; reset by last block

__device__ __forceinline__ uint32_t smem_u32(const void* p) {
    uint32_t a;
    asm("{ .reg .u64 t; cvta.to.shared.u64 t, %1; cvt.u32.u64 %0, t; }"
        : "=r"(a) : "l"(p));
    return a;
}

__device__ __forceinline__ void mbar_init(uint32_t mbar, uint32_t count) {
    asm volatile("mbarrier.init.shared.b64 [%0], %1;" :: "r"(mbar), "r"(count) : "memory");
}

__device__ __forceinline__ void mbar_expect_tx(uint32_t mbar, uint32_t bytes) {
    asm volatile("mbarrier.arrive.expect_tx.shared.b64 _, [%0], %1;"
                 :: "r"(mbar), "r"(bytes) : "memory");
}

__device__ __forceinline__ void bulk_g2s(uint32_t dst_smem, const void* src, uint32_t bytes,
                                         uint32_t mbar) {
    asm volatile("cp.async.bulk.shared::cta.global.mbarrier::complete_tx::bytes "
                 "[%0], [%1], %2, [%3];"
                 :: "r"(dst_smem), "l"(src), "r"(bytes), "r"(mbar) : "memory");
}

__device__ __forceinline__ void mbar_wait(uint32_t mbar, uint32_t phase) {
    asm volatile(
        "{\n\t"
        ".reg .pred P;\n\t"
        "WAIT_%=:\n\t"
        "mbarrier.try_wait.parity.acquire.cta.shared::cta.b64 P, [%0], %1, 0x989680;\n\t"
        "@!P bra WAIT_%=;\n\t"
        "}"
        :: "r"(mbar), "r"(phase) : "memory");
}

__device__ __forceinline__ float row_term(float a, float b, float c, int yt, float w) {
    // argmax with first-occurrence tie-breaking (strict >)
    int pred = 0;
    float best = a;
    if (b > best) { best = b; pred = 1; }
    if (c > best) { pred = 2; }
    float picked = (yt == 0) ? a : ((yt == 1) ? b : c);
    int d = pred - yt;
    bool penal = (d == 2) || (d == -2);
    return penal ? (w * picked) : picked;
}

// ---- shared tail: block partial -> g_partials -> last block folds ----
__device__ __forceinline__ void reduce_and_finish(float acc, float* out, float inv_n_neg,
                                                  float* s_red, bool* s_last) {
    #pragma unroll
    for (int off = 16; off > 0; off >>= 1)
        acc += __shfl_down_sync(0xFFFFFFFFu, acc, off);

    int lane = threadIdx.x & 31;
    int wid  = threadIdx.x >> 5;
    if (lane == 0) s_red[wid] = acc;
    __syncthreads();

    if (wid == 0) {
        float v = (lane < NTHREADS / 32) ? s_red[lane] : 0.0f;
        #pragma unroll
        for (int off = 16; off > 0; off >>= 1)
            v += __shfl_down_sync(0xFFFFFFFFu, v, off);
        if (lane == 0) {
            g_partials[blockIdx.x] = v;
            __threadfence();
            unsigned int prev = atomicAdd(&g_done_count, 1u);
            *s_last = (prev == (unsigned int)(gridDim.x - 1));
        }
    }
    __syncthreads();

    if (*s_last) {
        float v = 0.0f;
        for (int k = threadIdx.x; k < (int)gridDim.x; k += NTHREADS)
            v += g_partials[k];
        #pragma unroll
        for (int off = 16; off > 0; off >>= 1)
            v += __shfl_down_sync(0xFFFFFFFFu, v, off);
        if (lane == 0) s_red[wid] = v;
        __syncthreads();
        if (wid == 0) {
            float t = (lane < NTHREADS / 32) ? s_red[lane] : 0.0f;
            #pragma unroll
            for (int off = 16; off > 0; off >>= 1)
                t += __shfl_down_sync(0xFFFFFFFFu, t, off);
            if (lane == 0) {
                out[0] = t * inv_n_neg;   // = -sum / N
                g_done_count = 0u;        // reset for next graph replay
            }
        }
    }
}

// ---- TMA-pipelined kernel (exact shape: n == NBLOCKS*TILES_PER_BLOCK*ROWS_PER_TILE) ----
__global__ void __launch_bounds__(NTHREADS)
nll_tma_kernel(const float* __restrict__ pre,
               const int* __restrict__ y,
               const float* __restrict__ wp,
               float* __restrict__ out,
               float inv_n_neg) {
    __shared__ alignas(16) float s_pre[2][ROWS_PER_TILE * 3];
    __shared__ alignas(16) int   s_y[2][ROWS_PER_TILE];
    __shared__ alignas(8)  unsigned long long s_mbar[2];
    __shared__ float s_red[NTHREADS / 32];
    __shared__ bool  s_last;

    const float w = *wp;
    const int tid = threadIdx.x;
    const long long base_row = (long long)blockIdx.x * (TILES_PER_BLOCK * ROWS_PER_TILE);

    uint32_t mb0 = smem_u32(&s_mbar[0]);
    uint32_t mb1 = smem_u32(&s_mbar[1]);

    if (tid == 0) {
        mbar_init(mb0, 1);
        mbar_init(mb1, 1);
        asm volatile("fence.proxy.async.shared::cta;" ::: "memory");
    }
    __syncthreads();

    // prefill both stages
    if (tid == 0) {
        #pragma unroll
        for (int i = 0; i < 2; i++) {
            uint32_t mb = (i == 0) ? mb0 : mb1;
            long long r0 = base_row + (long long)i * ROWS_PER_TILE;
            mbar_expect_tx(mb, STAGE_TX_BYTES);
            bulk_g2s(smem_u32(&s_pre[i][0]), pre + r0 * 3, PRE_TILE_BYTES, mb);
            bulk_g2s(smem_u32(&s_y[i][0]),   y + r0,       Y_TILE_BYTES,   mb);
        }
    }

    float acc = 0.0f;

    for (int i = 0; i < TILES_PER_BLOCK; i++) {
        const int st = i & 1;
        const uint32_t mb = st ? mb1 : mb0;
        mbar_wait(mb, (i >> 1) & 1);

        #pragma unroll
        for (int k = 0; k < ROWS_PER_TILE / NTHREADS; k++) {
            int r = tid + k * NTHREADS;
            float a = s_pre[st][r * 3 + 0];
            float b = s_pre[st][r * 3 + 1];
            float c = s_pre[st][r * 3 + 2];
            acc += row_term(a, b, c, s_y[st][r], w);
        }
        __syncthreads();   // all threads done with this stage's smem

        if (tid == 0 && i + 2 < TILES_PER_BLOCK) {
            long long r0 = base_row + (long long)(i + 2) * ROWS_PER_TILE;
            mbar_expect_tx(mb, STAGE_TX_BYTES);
            bulk_g2s(smem_u32(&s_pre[st][0]), pre + r0 * 3, PRE_TILE_BYTES, mb);
            bulk_g2s(smem_u32(&s_y[st][0]),   y + r0,       Y_TILE_BYTES,   mb);
        }
    }

    reduce_and_finish(acc, out, inv_n_neg, s_red, &s_last);
}

// ---- generic fallback (any n) ----
__global__ void __launch_bounds__(NTHREADS)
nll_generic_kernel(const float* __restrict__ pre,
                   const int* __restrict__ y,
                   const float* __restrict__ wp,
                   float* __restrict__ out,
                   int n, float inv_n_neg) {
    __shared__ float s_red[NTHREADS / 32];
    __shared__ bool  s_last;

    const float4* p4 = reinterpret_cast<const float4*>(pre);
    const int4*   y4 = reinterpret_cast<const int4*>(y);
    const float w = *wp;

    const int nquad  = n >> 2;
    const int tid    = blockIdx.x * blockDim.x + threadIdx.x;
    const int stride = gridDim.x * blockDim.x;

    float acc = 0.0f;
    for (int q = tid; q < nquad; q += stride) {
        float4 f0 = p4[3 * q + 0];
        float4 f1 = p4[3 * q + 1];
        float4 f2 = p4[3 * q + 2];
        int4   yv = y4[q];
        acc += row_term(f0.x, f0.y, f0.z, yv.x, w);
        acc += row_term(f0.w, f1.x, f1.y, yv.y, w);
        acc += row_term(f1.z, f1.w, f2.x, yv.z, w);
        acc += row_term(f2.y, f2.z, f2.w, yv.w, w);
    }
    for (int i = (nquad << 2) + tid; i < n; i += stride)
        acc += row_term(pre[3 * i + 0], pre[3 * i + 1], pre[3 * i + 2], y[i], w);

    reduce_and_finish(acc, out, inv_n_neg, s_red, &s_last);
}

extern "C" void kernel_launch(void* const* d_in, const int* in_sizes, int n_in,
                              void* d_out, int out_size) {
    const float* pre = (const float*)d_in[0];
    const int*   y   = (const int*)d_in[1];
    const float* wp  = (const float*)d_in[2];
    float* out = (float*)d_out;

    const int n = in_sizes[1];   // y_true element count = number of rows

    if (n == NBLOCKS * TILES_PER_BLOCK * ROWS_PER_TILE) {
        nll_tma_kernel<<<NBLOCKS, NTHREADS>>>(pre, y, wp, out, -1.0f / (float)n);
    } else {
        nll_generic_kernel<<<NBLOCKS, NTHREADS>>>(pre, y, wp, out, n, -1.0f / (float)n);
    }
}

// round 6
// speedup vs baseline: 1.1006x; 1.0946x over previous
#include <cuda_runtime.h>
#include <cuda_bf16.h>

// Inputs (metadata order):
//   d_in[0]: pre     float32  [N, 3]   (log-softmax)
//   d_in[1]: y_true  int32    [N]
//   d_in[2]: weight  float32  scalar
// Output: float32 scalar = -sum(w_i * pre[i, y_i]) / N,
//   w_i = weight if |argmax(pre_i) - y_i| == 2 else 1.
//
// Structure: memset(out, 0) graph node, then one streaming kernel where each
// block atomicAdds its (deterministic) partial * (-1/N) into out. No global
// fence, no completion counter, no last-block fold -> kills the ~5us tail
// observed in R3/R5.

#define NBLOCKS 2048
#define NTHREADS 256

__device__ __forceinline__ float row_term(float a, float b, float c, int yt, float w) {
    // argmax with first-occurrence tie-breaking (strict >)
    int pred = 0;
    float best = a;
    if (b > best) { best = b; pred = 1; }
    if (c > best) { pred = 2; }
    float picked = (yt == 0) ? a : ((yt == 1) ? b : c);
    int d = pred - yt;
    bool penal = (d == 2) || (d == -2);
    return penal ? (w * picked) : picked;
}

__device__ __forceinline__ float quad_term(float4 f0, float4 f1, float4 f2,
                                           int4 yv, float w) {
    float t = 0.0f;
    t += row_term(f0.x, f0.y, f0.z, yv.x, w);
    t += row_term(f0.w, f1.x, f1.y, yv.y, w);
    t += row_term(f1.z, f1.w, f2.x, yv.z, w);
    t += row_term(f2.y, f2.z, f2.w, yv.w, w);
    return t;
}

__global__ void __launch_bounds__(NTHREADS)
nll_stream_kernel(const float* __restrict__ pre,
                  const int* __restrict__ y,
                  const float* __restrict__ wp,
                  float* __restrict__ out,
                  int n, float inv_n_neg) {
    const float4* p4 = reinterpret_cast<const float4*>(pre);
    const int4*   y4 = reinterpret_cast<const int4*>(y);
    const float w = *wp;

    const int nquad  = n >> 2;
    const int tid    = blockIdx.x * blockDim.x + threadIdx.x;
    const int stride = gridDim.x * blockDim.x;

    float acc = 0.0f;

    if (nquad == 4 * stride && (n & 3) == 0) {
        // Exact-fit path: each thread owns exactly 4 quads (this problem's N).
        #pragma unroll
        for (int u = 0; u < 4; u++) {
            int q = tid + u * stride;
            float4 f0 = __ldcs(&p4[3 * q + 0]);
            float4 f1 = __ldcs(&p4[3 * q + 1]);
            float4 f2 = __ldcs(&p4[3 * q + 2]);
            int4   yv = __ldcs(&y4[q]);
            acc += quad_term(f0, f1, f2, yv, w);
        }
    } else {
        // generic fallback
        for (int q = tid; q < nquad; q += stride) {
            float4 f0 = __ldcs(&p4[3 * q + 0]);
            float4 f1 = __ldcs(&p4[3 * q + 1]);
            float4 f2 = __ldcs(&p4[3 * q + 2]);
            acc += quad_term(f0, f1, f2, __ldcs(&y4[q]), w);
        }
        for (int i = (nquad << 2) + tid; i < n; i += stride)
            acc += row_term(pre[3 * i + 0], pre[3 * i + 1], pre[3 * i + 2], y[i], w);
    }

    // intra-block reduction
    #pragma unroll
    for (int off = 16; off > 0; off >>= 1)
        acc += __shfl_down_sync(0xFFFFFFFFu, acc, off);

    __shared__ float s[NTHREADS / 32];
    int lane = threadIdx.x & 31;
    int wid  = threadIdx.x >> 5;
    if (lane == 0) s[wid] = acc;
    __syncthreads();

    if (wid == 0) {
        float v = (lane < NTHREADS / 32) ? s[lane] : 0.0f;
        #pragma unroll
        for (int off = 16; off > 0; off >>= 1)
            v += __shfl_down_sync(0xFFFFFFFFu, v, off);
        if (lane == 0)
            atomicAdd(out, v * inv_n_neg);   // one REDG-class op per block
    }
}

extern "C" void kernel_launch(void* const* d_in, const int* in_sizes, int n_in,
                              void* d_out, int out_size) {
    const float* pre = (const float*)d_in[0];
    const int*   y   = (const int*)d_in[1];
    const float* wp  = (const float*)d_in[2];
    float* out = (float*)d_out;

    const int n = in_sizes[1];   // y_true element count = number of rows

    cudaMemsetAsync(out, 0, sizeof(float));   // clear poisoned output (capturable)
    nll_stream_kernel<<<NBLOCKS, NTHREADS>>>(pre, y, wp, out, n, -1.0f / (float)n);
}